// round 10
// baseline (speedup 1.0000x reference)
#include <cuda_runtime.h>
#include <cstdint>

#define DIM   512
#define BATCH 32
#define TT    2048
#define G4    2048              // 4*DIM
#define NBLK  128               // persistent blocks for recurrence
#define RTHR  512
#define GRPS  8                 // independent batch groups
#define GRPB  32                // blocks per group
#define GBAT  4                 // batches per group
#define HGRP  2048              // floats of h per group (512 dims x 4 b)

// ---------------- device scratch (no allocations allowed) ----------------
__device__ __align__(16) float g_xg[(size_t)TT * G4 * BATCH];   // [t][n][b]
__device__ __align__(16) float g_hbuf[4][GRPS * HGRP];          // 4-deep ring
__device__ unsigned g_flag[GRPS * GRPB * 8];   // flag per (group, dim-block)

typedef unsigned long long ull;

// ---------------- f32x2 helpers ----------------
__device__ __forceinline__ ull f2fma(ull a, ull b, ull c){
    ull d; asm("fma.rn.f32x2 %0, %1, %2, %3;" : "=l"(d) : "l"(a), "l"(b), "l"(c)); return d;
}
__device__ __forceinline__ ull pk2(float lo, float hi){
    ull r; asm("mov.b64 %0, {%1, %2};" : "=l"(r) : "f"(lo), "f"(hi)); return r;
}
__device__ __forceinline__ float2 upk(ull v){
    float2 f; asm("mov.b64 {%0, %1}, %2;" : "=f"(f.x), "=f"(f.y) : "l"(v)); return f;
}
__device__ __forceinline__ float hadd(ull v){ float2 f = upk(v); return f.x + f.y; }

__device__ __forceinline__ float sigf(float x){ return 1.0f / (1.0f + __expf(-x)); }
__device__ __forceinline__ float tanhfast(float x){
    float e = __expf(2.0f * x);              // inf-safe at both ends
    return 1.0f - 2.0f / (e + 1.0f);
}

// ---------------- scoped sync primitives ----------------
__device__ __forceinline__ void st_release(unsigned* p, unsigned v){
    asm volatile("st.release.gpu.global.u32 [%0], %1;" :: "l"(p), "r"(v) : "memory");
}
__device__ __forceinline__ unsigned ld_acquire(unsigned* p){
    unsigned v;
    asm volatile("ld.acquire.gpu.global.u32 %0, [%1];" : "=r"(v) : "l"(p) : "memory");
    return v;
}
__device__ __forceinline__ void cpa16(unsigned dst, const void* src){
    asm volatile("cp.async.cg.shared.global [%0], [%1], 16;" :: "r"(dst), "l"(src));
}
#define CP_COMMIT_WAIT() do { \
    asm volatile("cp.async.commit_group;"); \
    asm volatile("cp.async.wait_group 0;"); \
} while(0)

// =====================================================================
// Kernel 1: xg[t][n][b] GEMM (unchanged except init sizes).
// =====================================================================
__global__ void __launch_bounds__(256) gemm_xg_kernel(
    const float* __restrict__ x, const float* __restrict__ Wih,
    const float* __restrict__ bih, const float* __restrict__ bhh)
{
    __shared__ float As[8][128];
    __shared__ float Bs[8][128];
    const int tid = threadIdx.x;

    if (blockIdx.x == 0 && blockIdx.y == 0){     // init (runs before rec kernel)
        for (int i = tid; i < GRPS * HGRP; i += 256) g_hbuf[0][i] = 0.0f;
        for (int i = tid; i < GRPS * GRPB * 8; i += 256) g_flag[i] = 0u;
    }

    const int bn0 = blockIdx.x * 128;
    const int bm0 = blockIdx.y * 128;
    const int tm0 = (tid >> 4) * 8;
    const int c4  = (tid & 15) * 4;

    const int lr = tid >> 1;
    const int lk = (tid & 1) * 4;
    const int m  = bm0 + lr;
    const float* ap = x + (size_t)(m & 31) * ((size_t)TT * DIM) + (size_t)(m >> 5) * DIM + lk;
    const float* bp = Wih + (size_t)(bn0 + lr) * DIM + lk;

    ull c2[4][8];
    #pragma unroll
    for (int i = 0; i < 4; i++)
        #pragma unroll
        for (int j = 0; j < 8; j++) c2[i][j] = 0ULL;

    float4 av = *(const float4*)ap;
    float4 bv = *(const float4*)bp;

    for (int k0 = 0; k0 < DIM; k0 += 8){
        As[lk+0][lr]=av.x; As[lk+1][lr]=av.y; As[lk+2][lr]=av.z; As[lk+3][lr]=av.w;
        Bs[lk+0][lr]=bv.x; Bs[lk+1][lr]=bv.y; Bs[lk+2][lr]=bv.z; Bs[lk+3][lr]=bv.w;
        __syncthreads();
        if (k0 + 8 < DIM){
            av = *(const float4*)(ap + k0 + 8);
            bv = *(const float4*)(bp + k0 + 8);
        }
        #pragma unroll
        for (int kk = 0; kk < 8; kk++){
            const ulonglong2* arow = (const ulonglong2*)&As[kk][tm0];
            ulonglong2 a01 = arow[0];
            ulonglong2 a23 = arow[1];
            float4 bl = *(const float4*)&Bs[kk][c4];
            float4 bh = *(const float4*)&Bs[kk][c4 + 64];
            ull bd[8];
            bd[0]=pk2(bl.x,bl.x); bd[1]=pk2(bl.y,bl.y); bd[2]=pk2(bl.z,bl.z); bd[3]=pk2(bl.w,bl.w);
            bd[4]=pk2(bh.x,bh.x); bd[5]=pk2(bh.y,bh.y); bd[6]=pk2(bh.z,bh.z); bd[7]=pk2(bh.w,bh.w);
            #pragma unroll
            for (int j = 0; j < 8; j++){
                c2[0][j] = f2fma(a01.x, bd[j], c2[0][j]);
                c2[1][j] = f2fma(a01.y, bd[j], c2[1][j]);
                c2[2][j] = f2fma(a23.x, bd[j], c2[2][j]);
                c2[3][j] = f2fma(a23.y, bd[j], c2[3][j]);
            }
        }
        __syncthreads();
    }

    float bias[8];
    #pragma unroll
    for (int j = 0; j < 8; j++){
        int n = bn0 + c4 + (j & 3) + ((j >> 2) << 6);
        bias[j] = bih[n] + bhh[n];
    }
    #pragma unroll
    for (int i = 0; i < 8; i++){
        int mg = bm0 + tm0 + i;
        size_t obase = (size_t)(mg >> 5) * ((size_t)G4 * BATCH) + (size_t)(mg & 31);
        #pragma unroll
        for (int j = 0; j < 8; j++){
            float2 pq = upk(c2[i >> 1][j]);
            float v = (i & 1) ? pq.y : pq.x;
            int n = bn0 + c4 + (j & 3) + ((j >> 2) << 6);
            g_xg[obase + (size_t)n * BATCH] = v + bias[j];
        }
    }
}

// =====================================================================
// Kernel 2: persistent recurrence with TWO time-interleaved groups per
// block. 8 groups x 4 batches; block (p = bx>>5, gb = bx&31) runs
// groups A=p and B=p+4 over dims [gb*16,+16). 512 threads = 16 warps;
// warp kh = k-slice [kh*32,+32); lane = (dl = l&7, bq = l>>3).
// Thread FMA: 4 gates x 2 dims (dl, dl+8) x 1 batch (bq) x 32 k.
// Warp-private h slices (stage + read by same warp). Reduce-A by
// warps 0-7 (+ owners warps 0-1), reduce-B by warps 8-15 (+ owners
// warps 8-9); the other half runs ahead, hiding the flag handoff.
// =====================================================================
__global__ void __launch_bounds__(RTHR) lstm_rec_kernel(
    const float* __restrict__ Whh, float* __restrict__ out)
{
    extern __shared__ float sm[];
    float* shW  = sm;                      // 64 rows x 516
    float* shHA = shW + 64 * 516;          // 2048
    float* shHB = shHA + HGRP;             // 2048
    float* shRA = shHB + HGRP;             // 16 x 264
    float* shRB = shRA + 16 * 264;         // 16 x 264
    float* shGA = shRB + 16 * 264;         // 288
    float* shGB = shGA + 288;              // 288

    const int tid  = threadIdx.x;
    const int bx   = blockIdx.x;
    const int gb   = bx & 31;
    const int p    = bx >> 5;
    const int gA   = p, gB = p + 4;
    const int kh   = tid >> 5;
    const int lane = tid & 31;
    const int dl   = lane & 7;
    const int bq   = lane >> 3;

    // Load this block's 64 W_hh rows into padded shared (once).
    for (int idx = tid; idx < 64 * 128; idx += RTHR){
        int rl = idx >> 7;                 // g*16 + dloc
        int k4 = idx & 127;
        int g = rl >> 4, dloc = rl & 15;
        *(float4*)(shW + rl * 516 + k4 * 4) =
            *(const float4*)(Whh + (size_t)(g * DIM + gb * 16 + dloc) * DIM + k4 * 4);
    }

    // 8 W row pointers: gates x {dl, dl+8}, k-slice kh*32
    const ulonglong2* w00 = (const ulonglong2*)(shW + (0*16 + dl    ) * 516 + kh * 32);
    const ulonglong2* w01 = (const ulonglong2*)(shW + (0*16 + dl + 8) * 516 + kh * 32);
    const ulonglong2* w10 = (const ulonglong2*)(shW + (1*16 + dl    ) * 516 + kh * 32);
    const ulonglong2* w11 = (const ulonglong2*)(shW + (1*16 + dl + 8) * 516 + kh * 32);
    const ulonglong2* w20 = (const ulonglong2*)(shW + (2*16 + dl    ) * 516 + kh * 32);
    const ulonglong2* w21 = (const ulonglong2*)(shW + (2*16 + dl + 8) * 516 + kh * 32);
    const ulonglong2* w30 = (const ulonglong2*)(shW + (3*16 + dl    ) * 516 + kh * 32);
    const ulonglong2* w31 = (const ulonglong2*)(shW + (3*16 + dl + 8) * 516 + kh * 32);

    const ulonglong2* hAp = ((const ulonglong2*)shHA) + kh * 32 + bq;
    const ulonglong2* hBp = ((const ulonglong2*)shHB) + kh * 32 + bq;

    const unsigned stgA =
        (unsigned)__cvta_generic_to_shared(shHA) + (unsigned)(kh * 32 + lane) * 16u;
    const unsigned stgB =
        (unsigned)__cvta_generic_to_shared(shHB) + (unsigned)(kh * 32 + lane) * 16u;
    const int stg_idx = kh * 32 + lane;    // float4 index within group image

    // poll pointers: producers of k-slice kh are group blocks 2kh, 2kh+1
    unsigned* pfA = &g_flag[(gA * GRPB + kh * 2 + (lane & 1)) * 8];
    unsigned* pfB = &g_flag[(gB * GRPB + kh * 2 + (lane & 1)) * 8];

    // reduce role: half A = tid<256 (r = tid), half B = tid>=256
    const int rr  = (tid < 256) ? tid : (tid - 256);
    const int rg  = rr >> 6;               // gate
    const int rd  = (rr >> 2) & 15;        // local dim
    const int rb  = rr & 3;                // local batch
    const int myg = (tid < 256) ? gA : gB;
    const size_t xoffs = (size_t)(rg * DIM + gb * 16 + rd) * BATCH
                       + (size_t)(myg * GBAT + rb);

    // owner roles: A owners = tid 0..63 (warps 0,1); B = 256..319 (8,9)
    const bool ownA = (tid < 64);
    const bool ownB = (tid >= 256 && tid < 320);
    const int  ol   = tid & 63;
    const int  od   = ol & 15, ob = ol >> 4;
    const int  Dd   = gb * 16 + od;
    const int  hwA  = gA * HGRP + (Dd >> 2) * (GBAT * 4) + ob * 4 + (Dd & 3);
    const int  hwB  = gB * HGRP + (Dd >> 2) * (GBAT * 4) + ob * 4 + (Dd & 3);
    float* outA = out + (size_t)(gA * GBAT + ob) * ((size_t)TT * DIM) + Dd;
    float* outB = out + (size_t)(gB * GBAT + ob) * ((size_t)TT * DIM) + Dd;
    unsigned* flagA = &g_flag[(gA * GRPB + gb) * 8];
    unsigned* flagB = &g_flag[(gB * GRPB + gb) * 8];

    float ccA = 0.0f, ccB = 0.0f;
    __syncthreads();                       // W ready

    for (int t = 0; t < TT; t++){
        // xg prefetch for my half's output (independent of h)
        float xv = __ldcg(g_xg + (size_t)t * ((size_t)G4 * BATCH) + xoffs);

        // ============================ GROUP A ============================
        if (lane < 2){ while (ld_acquire(pfA) < (unsigned)t) { } }
        __syncwarp();
        cpa16(stgA, (const float4*)g_hbuf[t & 3] + gA * (HGRP/4) + stg_idx);
        CP_COMMIT_WAIT();
        __syncwarp();
        {
            ull a00=0,a01=0,a10=0,a11=0,a20=0,a21=0,a30=0,a31=0;
            #pragma unroll
            for (int i = 0; i < 8; i++){
                ulonglong2 hv = hAp[i * 4];
                ulonglong2 v;
                v = w00[i]; a00 = f2fma(hv.x, v.x, a00); a00 = f2fma(hv.y, v.y, a00);
                v = w01[i]; a01 = f2fma(hv.x, v.x, a01); a01 = f2fma(hv.y, v.y, a01);
                v = w10[i]; a10 = f2fma(hv.x, v.x, a10); a10 = f2fma(hv.y, v.y, a10);
                v = w11[i]; a11 = f2fma(hv.x, v.x, a11); a11 = f2fma(hv.y, v.y, a11);
                v = w20[i]; a20 = f2fma(hv.x, v.x, a20); a20 = f2fma(hv.y, v.y, a20);
                v = w21[i]; a21 = f2fma(hv.x, v.x, a21); a21 = f2fma(hv.y, v.y, a21);
                v = w30[i]; a30 = f2fma(hv.x, v.x, a30); a30 = f2fma(hv.y, v.y, a30);
                v = w31[i]; a31 = f2fma(hv.x, v.x, a31); a31 = f2fma(hv.y, v.y, a31);
            }
            float* rw = shRA + kh * 264 + dl * 4 + bq;
            rw[  0]      = hadd(a00); rw[ 32]      = hadd(a01);
            rw[ 64]      = hadd(a10); rw[ 96]      = hadd(a11);
            rw[128]      = hadd(a20); rw[160]      = hadd(a21);
            rw[192]      = hadd(a30); rw[224]      = hadd(a31);
        }
        __syncthreads();                   // bar1A: all A partials in

        if (tid < 256){                    // reduce A: warps 0-7
            float s = xv;
            const float* rp = shRA + tid;
            #pragma unroll
            for (int k = 0; k < 16; k++) s += rp[k * 264];
            shGA[tid] = (rg == 2) ? tanhfast(s) : sigf(s);
            asm volatile("bar.sync 2, 256;");
            if (ownA){
                float iv = shGA[      od*4 + ob];
                float fv = shGA[ 64 + od*4 + ob];
                float gv = shGA[128 + od*4 + ob];
                float ov = shGA[192 + od*4 + ob];
                ccA = fv * ccA + iv * gv;
                float hv = ov * tanhfast(ccA);
                g_hbuf[(t + 1) & 3][hwA] = hv;
                asm volatile("bar.sync 3, 64;");
                if (tid == 0 && t + 1 < TT) st_release(flagA, (unsigned)(t + 1));
                outA[(size_t)t * DIM] = hv;
            }
        }

        // ============================ GROUP B ============================
        if (lane < 2){ while (ld_acquire(pfB) < (unsigned)t) { } }
        __syncwarp();
        cpa16(stgB, (const float4*)g_hbuf[t & 3] + gB * (HGRP/4) + stg_idx);
        CP_COMMIT_WAIT();
        __syncwarp();
        {
            ull a00=0,a01=0,a10=0,a11=0,a20=0,a21=0,a30=0,a31=0;
            #pragma unroll
            for (int i = 0; i < 8; i++){
                ulonglong2 hv = hBp[i * 4];
                ulonglong2 v;
                v = w00[i]; a00 = f2fma(hv.x, v.x, a00); a00 = f2fma(hv.y, v.y, a00);
                v = w01[i]; a01 = f2fma(hv.x, v.x, a01); a01 = f2fma(hv.y, v.y, a01);
                v = w10[i]; a10 = f2fma(hv.x, v.x, a10); a10 = f2fma(hv.y, v.y, a10);
                v = w11[i]; a11 = f2fma(hv.x, v.x, a11); a11 = f2fma(hv.y, v.y, a11);
                v = w20[i]; a20 = f2fma(hv.x, v.x, a20); a20 = f2fma(hv.y, v.y, a20);
                v = w21[i]; a21 = f2fma(hv.x, v.x, a21); a21 = f2fma(hv.y, v.y, a21);
                v = w30[i]; a30 = f2fma(hv.x, v.x, a30); a30 = f2fma(hv.y, v.y, a30);
                v = w31[i]; a31 = f2fma(hv.x, v.x, a31); a31 = f2fma(hv.y, v.y, a31);
            }
            float* rw = shRB + kh * 264 + dl * 4 + bq;
            rw[  0]      = hadd(a00); rw[ 32]      = hadd(a01);
            rw[ 64]      = hadd(a10); rw[ 96]      = hadd(a11);
            rw[128]      = hadd(a20); rw[160]      = hadd(a21);
            rw[192]      = hadd(a30); rw[224]      = hadd(a31);
        }
        __syncthreads();                   // bar1B: all B partials in

        if (tid >= 256){                   // reduce B: warps 8-15
            float s = xv;
            const float* rp = shRB + (tid - 256);
            #pragma unroll
            for (int k = 0; k < 16; k++) s += rp[k * 264];
            shGB[tid - 256] = (rg == 2) ? tanhfast(s) : sigf(s);
            asm volatile("bar.sync 4, 256;");
            if (ownB){
                float iv = shGB[      od*4 + ob];
                float fv = shGB[ 64 + od*4 + ob];
                float gv = shGB[128 + od*4 + ob];
                float ov = shGB[192 + od*4 + ob];
                ccB = fv * ccB + iv * gv;
                float hv = ov * tanhfast(ccB);
                g_hbuf[(t + 1) & 3][hwB] = hv;
                asm volatile("bar.sync 5, 64;");
                if (tid == 256 && t + 1 < TT) st_release(flagB, (unsigned)(t + 1));
                outB[(size_t)t * DIM] = hv;
            }
        }
    }
}

// =====================================================================
extern "C" void kernel_launch(void* const* d_in, const int* in_sizes, int n_in,
                              void* d_out, int out_size)
{
    (void)in_sizes; (void)n_in; (void)out_size;
    const float* x    = (const float*)d_in[0];
    const float* Wih  = (const float*)d_in[1];
    const float* Whh  = (const float*)d_in[2];
    const float* bih  = (const float*)d_in[3];
    const float* bhh  = (const float*)d_in[4];
    float* out = (float*)d_out;

    // 64*516 + 2*2048 + 2*16*264 + 2*288 = 46144 floats = 184576 bytes
    cudaFuncSetAttribute(lstm_rec_kernel,
                         cudaFuncAttributeMaxDynamicSharedMemorySize, 184576);

    dim3 ggrid(G4 / 128, (BATCH * TT) / 128);
    gemm_xg_kernel<<<ggrid, 256>>>(x, Wih, bih, bhh);
    lstm_rec_kernel<<<NBLK, RTHR, 184576>>>(Whh, out);
}

// round 11
// speedup vs baseline: 1.4960x; 1.4960x over previous
#include <cuda_runtime.h>
#include <cstdint>

#define DIM   512
#define BATCH 32
#define TT    2048
#define NBLK  128
#define RTHR  512

// ---------------- device scratch (no allocations allowed) ----------------
__device__ __align__(16) float g_xT[(size_t)TT * DIM * BATCH];  // [t][k4][b][4]
__device__ __align__(16) float g_hbuf[4][DIM * BATCH];          // [k4][b][4]
__device__ unsigned g_flag[NBLK * 8];   // one flag per block, 32B apart

typedef unsigned long long ull;

// ---------------- f32x2 helpers ----------------
__device__ __forceinline__ ull f2fma(ull a, ull b, ull c){
    ull d; asm("fma.rn.f32x2 %0, %1, %2, %3;" : "=l"(d) : "l"(a), "l"(b), "l"(c)); return d;
}
__device__ __forceinline__ float2 upk(ull v){
    float2 f; asm("mov.b64 {%0, %1}, %2;" : "=f"(f.x), "=f"(f.y) : "l"(v)); return f;
}
__device__ __forceinline__ float hadd(ull v){ float2 f = upk(v); return f.x + f.y; }

__device__ __forceinline__ float sigf(float x){ return 1.0f / (1.0f + __expf(-x)); }
__device__ __forceinline__ float tanhfast(float x){
    float e = __expf(2.0f * x);              // inf-safe at both ends
    return 1.0f - 2.0f / (e + 1.0f);
}

// ---------------- scoped sync primitives ----------------
__device__ __forceinline__ void st_release(unsigned* p, unsigned v){
    asm volatile("st.release.gpu.global.u32 [%0], %1;" :: "l"(p), "r"(v) : "memory");
}
__device__ __forceinline__ unsigned ld_acquire(unsigned* p){
    unsigned v;
    asm volatile("ld.acquire.gpu.global.u32 %0, [%1];" : "=r"(v) : "l"(p) : "memory");
    return v;
}
__device__ __forceinline__ void cpa16(unsigned dst, const void* src){
    asm volatile("cp.async.cg.shared.global [%0], [%1], 16;" :: "r"(dst), "l"(src));
}

// =====================================================================
// Kernel 1: transpose x[b][t][k] -> xT[t][k4][b][4]; block 0 inits state.
// gidx enumerates f4 = t*4096 + k4*32 + b  -> writes fully coalesced.
// =====================================================================
__global__ void __launch_bounds__(256) xt_kernel(const float* __restrict__ x)
{
    if (blockIdx.x == 0){
        int tid = threadIdx.x;
        for (int i = tid; i < DIM * BATCH; i += 256) g_hbuf[0][i] = 0.0f;
        for (int i = tid; i < NBLK; i += 256) g_flag[i * 8] = 0u;
    }
    size_t gidx = (size_t)blockIdx.x * 256 + threadIdx.x;
    int b  = (int)(gidx & 31);
    int k4 = (int)((gidx >> 5) & 127);
    int t  = (int)(gidx >> 12);
    float4 v = *(const float4*)(x + (size_t)b * ((size_t)TT * DIM)
                                  + (size_t)t * DIM + k4 * 4);
    ((float4*)g_xT)[gidx] = v;
}

// =====================================================================
// Kernel 2: fused persistent LSTM. 128 blocks x 512 threads (16 warps).
// Block bx owns dims dg = bx*4+dl (4 dims x 4 gates); W_hh + W_ih slices
// (16 rows each) in shared, layout [k4][rl][4] (conflict-free reads).
// Warp kh owns k-slice [kh*32,+32); lane = (bq = l&7, dl = l>>3).
// Per step: wait x (staged last iter) -> x-FMA -> prefetch x(t+1) ->
// poll 8 producer flags -> cp.async h slice -> h-FMA (same acc) ->
// partials -> reduce(+bias) -> owners c/h update -> release.
// =====================================================================
__global__ void __launch_bounds__(RTHR) lstm_rec_kernel(
    const float* __restrict__ Wih, const float* __restrict__ Whh,
    const float* __restrict__ bih, const float* __restrict__ bhh,
    float* __restrict__ out)
{
    extern __shared__ float sm[];
    float* shW = sm;              // 16384 fl: f4 idx k4*16+rl ; +2048 f4 = Wih
    float* shH = sm + 16384;      // 16384 fl: [k4][b][4]
    float* shX = sm + 32768;      // 16384 fl: [k4][b][4]
    float* shR = sm + 49152;      // 16 rows x 527
    float* shG = sm + 57584;      // 512: [g][dloc 4][b 32]... R7 layout g*128+rd*32+b
    float* shB = sm + 58096;      // 16 biases

    const int tid  = threadIdx.x;
    const int bx   = blockIdx.x;
    const int kh   = tid >> 5;
    const int lane = tid & 31;
    const int bq   = lane & 7;
    const int dl   = lane >> 3;

    // Load W_hh and W_ih slices into [k4][rl] layout (once).
    for (int idx = tid; idx < 4096; idx += RTHR){
        int half = idx >> 11;              // 0 = hh, 1 = ih
        int rem  = idx & 2047;
        int rl   = rem >> 7;               // g*4 + dloc
        int k4   = rem & 127;
        int g = rl >> 2, dloc = rl & 3;
        const float* src = (half ? Wih : Whh)
                         + (size_t)(g * DIM + bx * 4 + dloc) * DIM + k4 * 4;
        ((float4*)shW)[half * 2048 + k4 * 16 + rl] = *(const float4*)src;
    }
    if (tid < 16){
        int n = (tid >> 2) * DIM + bx * 4 + (tid & 3);
        shB[tid] = bih[n] + bhh[n];
    }

    // FMA pointers: f4 idx = (kh*8+i)*16 + g*4 + dl
    const ulonglong2* WH = (const ulonglong2*)shW;
    const ulonglong2* wh0 = WH + kh*128 + 0*4 + dl;
    const ulonglong2* wh1 = WH + kh*128 + 1*4 + dl;
    const ulonglong2* wh2 = WH + kh*128 + 2*4 + dl;
    const ulonglong2* wh3 = WH + kh*128 + 3*4 + dl;
    const ulonglong2* wx0 = wh0 + 2048;
    const ulonglong2* wx1 = wh1 + 2048;
    const ulonglong2* wx2 = wh2 + 2048;
    const ulonglong2* wx3 = wh3 + 2048;
    const ulonglong2* hp = ((const ulonglong2*)shH) + kh * 256 + bq;
    const ulonglong2* xp = ((const ulonglong2*)shX) + kh * 256 + bq;

    // staging (warp-private 4KB slices)
    const unsigned stH =
        (unsigned)__cvta_generic_to_shared(shH) + (unsigned)(kh * 256 + lane) * 16u;
    const unsigned stX =
        (unsigned)__cvta_generic_to_shared(shX) + (unsigned)(kh * 256 + lane) * 16u;
    const int stg_src = kh * 256 + lane;   // f4 index within a 4096-f4 slice

    // poll: producers of k-slice kh are blocks kh*8 .. kh*8+7
    unsigned* pf = &g_flag[(kh * 8 + (lane & 7)) * 8];

    // reduce role (R7): warp kh = (rg = kh>>2 gate, rd = kh&3 dim-local)
    const int rg = kh >> 2;
    const int rd = kh & 3;
    const float* rp = shR + (rg * 4 + (lane >> 3)) * 527 + rd * 8 + (lane & 7);
    const float bias_r = (tid < RTHR) ? 0.f : 0.f;  // placeholder (bias via shB)

    // owner role (tid < 128): pb = tid&31, pd = tid>>5
    const int pb = tid & 31;
    const int pd = tid >> 5;
    const int dgp = bx * 4 + pd;
    float* outp = out + (size_t)pb * ((size_t)TT * DIM) + dgp;
    const int hwidx = bx * 128 + pb * 4 + pd;     // [k4][b][4] flat index

    float cc = 0.0f;
    float hv = 0.0f;
    (void)bias_r;

    // prologue: stage x for t = 0
    {
        const float4* xs = (const float4*)g_xT + stg_src;
        #pragma unroll
        for (int q = 0; q < 8; q++) cpa16(stX + q * 512u, xs + q * 32);
        asm volatile("cp.async.commit_group;");
    }
    __syncthreads();                       // W + biases ready

    for (int t = 0; t < TT; t++){
        // ---- wait for x slice (staged in previous iter / prologue) ----
        asm volatile("cp.async.wait_group 0;");
        __syncwarp();

        // ---- x-FMA: 4 gates x 4 batches over 32 k (independent of h) ----
        ull acc[4][4];
        #pragma unroll
        for (int g = 0; g < 4; g++)
            #pragma unroll
            for (int j = 0; j < 4; j++) acc[g][j] = 0ULL;

        #pragma unroll
        for (int i = 0; i < 8; i++){
            ulonglong2 x0 = xp[i * 32];
            ulonglong2 x1 = xp[i * 32 + 8];
            ulonglong2 x2 = xp[i * 32 + 16];
            ulonglong2 x3 = xp[i * 32 + 24];
            ulonglong2 v0 = wx0[i * 16], v1 = wx1[i * 16];
            ulonglong2 v2 = wx2[i * 16], v3 = wx3[i * 16];
            acc[0][0]=f2fma(x0.x,v0.x,acc[0][0]); acc[0][0]=f2fma(x0.y,v0.y,acc[0][0]);
            acc[0][1]=f2fma(x1.x,v0.x,acc[0][1]); acc[0][1]=f2fma(x1.y,v0.y,acc[0][1]);
            acc[0][2]=f2fma(x2.x,v0.x,acc[0][2]); acc[0][2]=f2fma(x2.y,v0.y,acc[0][2]);
            acc[0][3]=f2fma(x3.x,v0.x,acc[0][3]); acc[0][3]=f2fma(x3.y,v0.y,acc[0][3]);
            acc[1][0]=f2fma(x0.x,v1.x,acc[1][0]); acc[1][0]=f2fma(x0.y,v1.y,acc[1][0]);
            acc[1][1]=f2fma(x1.x,v1.x,acc[1][1]); acc[1][1]=f2fma(x1.y,v1.y,acc[1][1]);
            acc[1][2]=f2fma(x2.x,v1.x,acc[1][2]); acc[1][2]=f2fma(x2.y,v1.y,acc[1][2]);
            acc[1][3]=f2fma(x3.x,v1.x,acc[1][3]); acc[1][3]=f2fma(x3.y,v1.y,acc[1][3]);
            acc[2][0]=f2fma(x0.x,v2.x,acc[2][0]); acc[2][0]=f2fma(x0.y,v2.y,acc[2][0]);
            acc[2][1]=f2fma(x1.x,v2.x,acc[2][1]); acc[2][1]=f2fma(x1.y,v2.y,acc[2][1]);
            acc[2][2]=f2fma(x2.x,v2.x,acc[2][2]); acc[2][2]=f2fma(x2.y,v2.y,acc[2][2]);
            acc[2][3]=f2fma(x3.x,v2.x,acc[2][3]); acc[2][3]=f2fma(x3.y,v2.y,acc[2][3]);
            acc[3][0]=f2fma(x0.x,v3.x,acc[3][0]); acc[3][0]=f2fma(x0.y,v3.y,acc[3][0]);
            acc[3][1]=f2fma(x1.x,v3.x,acc[3][1]); acc[3][1]=f2fma(x1.y,v3.y,acc[3][1]);
            acc[3][2]=f2fma(x2.x,v3.x,acc[3][2]); acc[3][2]=f2fma(x2.y,v3.y,acc[3][2]);
            acc[3][3]=f2fma(x3.x,v3.x,acc[3][3]); acc[3][3]=f2fma(x3.y,v3.y,acc[3][3]);
        }

        // ---- prefetch x for t+1 (x LDS all complete: in-order issue) ----
        {
            int tn = (t + 1 < TT) ? (t + 1) : t;
            const float4* xs = (const float4*)g_xT + (size_t)tn * 4096 + stg_src;
            #pragma unroll
            for (int q = 0; q < 8; q++) cpa16(stX + q * 512u, xs + q * 32);
            asm volatile("cp.async.commit_group;");
        }

        // ---- poll my 8 producers, then stage h slice ----
        if (lane < 8){
            while (ld_acquire(pf) < (unsigned)t) { }
        }
        __syncwarp();
        {
            const float4* hs = (const float4*)g_hbuf[t & 3] + stg_src;
            #pragma unroll
            for (int q = 0; q < 8; q++) cpa16(stH + q * 512u, hs + q * 32);
            asm volatile("cp.async.commit_group;");
            asm volatile("cp.async.wait_group 0;");
        }
        __syncwarp();

        // ---- h-FMA into same accumulators ----
        #pragma unroll
        for (int i = 0; i < 8; i++){
            ulonglong2 h0 = hp[i * 32];
            ulonglong2 h1 = hp[i * 32 + 8];
            ulonglong2 h2 = hp[i * 32 + 16];
            ulonglong2 h3 = hp[i * 32 + 24];
            ulonglong2 v0 = wh0[i * 16], v1 = wh1[i * 16];
            ulonglong2 v2 = wh2[i * 16], v3 = wh3[i * 16];
            acc[0][0]=f2fma(h0.x,v0.x,acc[0][0]); acc[0][0]=f2fma(h0.y,v0.y,acc[0][0]);
            acc[0][1]=f2fma(h1.x,v0.x,acc[0][1]); acc[0][1]=f2fma(h1.y,v0.y,acc[0][1]);
            acc[0][2]=f2fma(h2.x,v0.x,acc[0][2]); acc[0][2]=f2fma(h2.y,v0.y,acc[0][2]);
            acc[0][3]=f2fma(h3.x,v0.x,acc[0][3]); acc[0][3]=f2fma(h3.y,v0.y,acc[0][3]);
            acc[1][0]=f2fma(h0.x,v1.x,acc[1][0]); acc[1][0]=f2fma(h0.y,v1.y,acc[1][0]);
            acc[1][1]=f2fma(h1.x,v1.x,acc[1][1]); acc[1][1]=f2fma(h1.y,v1.y,acc[1][1]);
            acc[1][2]=f2fma(h2.x,v1.x,acc[1][2]); acc[1][2]=f2fma(h2.y,v1.y,acc[1][2]);
            acc[1][3]=f2fma(h3.x,v1.x,acc[1][3]); acc[1][3]=f2fma(h3.y,v1.y,acc[1][3]);
            acc[2][0]=f2fma(h0.x,v2.x,acc[2][0]); acc[2][0]=f2fma(h0.y,v2.y,acc[2][0]);
            acc[2][1]=f2fma(h1.x,v2.x,acc[2][1]); acc[2][1]=f2fma(h1.y,v2.y,acc[2][1]);
            acc[2][2]=f2fma(h2.x,v2.x,acc[2][2]); acc[2][2]=f2fma(h2.y,v2.y,acc[2][2]);
            acc[2][3]=f2fma(h3.x,v2.x,acc[2][3]); acc[2][3]=f2fma(h3.y,v2.y,acc[2][3]);
            acc[3][0]=f2fma(h0.x,v3.x,acc[3][0]); acc[3][0]=f2fma(h0.y,v3.y,acc[3][0]);
            acc[3][1]=f2fma(h1.x,v3.x,acc[3][1]); acc[3][1]=f2fma(h1.y,v3.y,acc[3][1]);
            acc[3][2]=f2fma(h2.x,v3.x,acc[3][2]); acc[3][2]=f2fma(h2.y,v3.y,acc[3][2]);
            acc[3][3]=f2fma(h3.x,v3.x,acc[3][3]); acc[3][3]=f2fma(h3.y,v3.y,acc[3][3]);
        }

        // ---- partials: shR[(g*4+j)*527 + kh*33 + lane] ----
        #pragma unroll
        for (int g = 0; g < 4; g++)
            #pragma unroll
            for (int j = 0; j < 4; j++)
                shR[(g*4 + j) * 527 + kh * 33 + lane] = hadd(acc[g][j]);
        __syncthreads();                   // bar1: all partials in

        // ---- reduce (warp = gate x dim, lane = batch) + bias + nonlin ----
        {
            float s = shB[rg * 4 + rd];
            #pragma unroll
            for (int k = 0; k < 16; k++) s += rp[k * 33];
            shG[rg * 128 + rd * 32 + lane] = (rg == 2) ? tanhfast(s) : sigf(s);
        }
        __syncthreads();                   // bar2: gates ready

        // ---- owners: c/h update, store h ----
        if (tid < 128){
            float iv = shG[  0 + pd * 32 + pb];
            float fv = shG[128 + pd * 32 + pb];
            float gv = shG[256 + pd * 32 + pb];
            float ov = shG[384 + pd * 32 + pb];
            cc = fv * cc + iv * gv;
            hv = ov * tanhfast(cc);
            g_hbuf[(t + 1) & 3][hwidx] = hv;
        }
        __syncthreads();                   // bar3: h stores done block-wide

        if (t + 1 < TT){
            if (tid == 0) st_release(&g_flag[bx * 8], (unsigned)(t + 1));
        }
        // out store overlaps the next step's x-FMA/polls
        if (tid < 128) outp[(size_t)t * DIM] = hv;
    }
}

// =====================================================================
extern "C" void kernel_launch(void* const* d_in, const int* in_sizes, int n_in,
                              void* d_out, int out_size)
{
    (void)in_sizes; (void)n_in; (void)out_size;
    const float* x    = (const float*)d_in[0];
    const float* Wih  = (const float*)d_in[1];
    const float* Whh  = (const float*)d_in[2];
    const float* bih  = (const float*)d_in[3];
    const float* bhh  = (const float*)d_in[4];
    float* out = (float*)d_out;

    // 16384 + 16384 + 16384 + 8432 + 512 + 16 = 58112 floats = 232448 bytes
    cudaFuncSetAttribute(lstm_rec_kernel,
                         cudaFuncAttributeMaxDynamicSharedMemorySize, 232448);

    xt_kernel<<<(TT * DIM * BATCH / 4) / 256, 256>>>(x);
    lstm_rec_kernel<<<NBLK, RTHR, 232448>>>(Wih, Whh, bih, bhh, out);
}